// round 5
// baseline (speedup 1.0000x reference)
#include <cuda_runtime.h>
#include <math.h>

// Problem constants
#define BB   256
#define TT   1000
#define HH   64
#define GG   256   // 4*H
#define DIN  22
#define DH   128   // 2*H

// Scratch (device globals; no runtime allocation allowed)
__device__ float g_xw[(size_t)2 * BB * TT * GG];      // [dir][b][t][g]
__device__ float g_hbuf[2][(size_t)BB * TT * DH];     // ping-pong layer outputs

typedef unsigned long long u64;

// ---- packed f32x2 helpers (FFMA2 pattern; exact fp32 math) ----
__device__ __forceinline__ u64 pack2(float lo, float hi) {
    u64 r; asm("mov.b64 %0, {%1, %2};" : "=l"(r) : "f"(lo), "f"(hi)); return r;
}
__device__ __forceinline__ void unpack2(u64 v, float& lo, float& hi) {
    asm("mov.b64 {%0, %1}, %2;" : "=f"(lo), "=f"(hi) : "l"(v));
}
__device__ __forceinline__ u64 splat2(float x) {
    u64 r; asm("mov.b64 %0, {%1, %1};" : "=l"(r) : "f"(x)); return r;
}
__device__ __forceinline__ u64 fma2(u64 a, u64 b, u64 c) {
    u64 d; asm("fma.rn.f32x2 %0, %1, %2, %3;" : "=l"(d) : "l"(a), "l"(b), "l"(c));
    return d;
}
__device__ __forceinline__ u64 add2(u64 a, u64 b) {
    u64 d; asm("add.rn.f32x2 %0, %1, %2;" : "=l"(d) : "l"(a), "l"(b));
    return d;
}
// shuffle both 32-bit halves of a u64 across lanes (xor mode)
__device__ __forceinline__ u64 shfl2(u64 v, int m) {
    float lo, hi; unpack2(v, lo, hi);
    lo = __shfl_xor_sync(0xFFFFFFFFu, lo, m);
    hi = __shfl_xor_sync(0xFFFFFFFFu, hi, m);
    return pack2(lo, hi);
}

__device__ __forceinline__ float ex2a(float x) {
    float y; asm("ex2.approx.f32 %0, %1;" : "=f"(y) : "f"(x)); return y;
}
__device__ __forceinline__ float rcpa(float x) {
    float y; asm("rcp.approx.f32 %0, %1;" : "=f"(y) : "f"(x)); return y;
}

#define L2E  1.4426950408889634f

__device__ __forceinline__ float fast_sig(float x) {
    return rcpa(1.0f + ex2a(-L2E * x));
}
__device__ __forceinline__ float fast_tanh(float x) {
    return fmaf(2.0f, rcpa(1.0f + ex2a(-2.0f * L2E * x)), -1.0f);
}

// ---------------------------------------------------------------------------
// Layer-0 input projection
// ---------------------------------------------------------------------------
__global__ __launch_bounds__(256) void gemm0_kernel(
    const float* __restrict__ x,       // (B, 22, T)
    const float* __restrict__ w,       // (2, 256, 22)
    const float* __restrict__ bih,     // (4, 2, 256)
    const float* __restrict__ bhh)     // (4, 2, 256)
{
    const int b = blockIdx.x, dir = blockIdx.y;
    const int g = threadIdx.x;
    __shared__ float xs[DIN][16];

    float wr[DIN];
#pragma unroll
    for (int d = 0; d < DIN; d++) wr[d] = w[(dir * GG + g) * DIN + d];
    const float bias = bih[dir * GG + g] + bhh[dir * GG + g];

    const float* xb = x + (size_t)b * DIN * TT;
    float* out = g_xw + ((size_t)(dir * BB + b)) * TT * GG;

    for (int tc = 0; tc < TT; tc += 16) {
        for (int e = threadIdx.x; e < DIN * 16; e += 256) {
            int d = e >> 4, tt = e & 15;
            int t = tc + tt;
            xs[d][tt] = (t < TT) ? xb[d * TT + t] : 0.0f;
        }
        __syncthreads();
        float acc[16];
#pragma unroll
        for (int tt = 0; tt < 16; tt++) acc[tt] = bias;
#pragma unroll
        for (int d = 0; d < DIN; d++) {
            float wd = wr[d];
#pragma unroll
            for (int tt = 0; tt < 16; tt++) acc[tt] = fmaf(wd, xs[d][tt], acc[tt]);
        }
#pragma unroll
        for (int tt = 0; tt < 16; tt++) {
            int t = tc + tt;
            if (t < TT) out[(size_t)t * GG + g] = acc[tt];
        }
        __syncthreads();
    }
}

// ---------------------------------------------------------------------------
// Layers 1..3 input projection, register-tiled f32x2, 512 threads.
// grid (B, 2, 2): (batch, dir, t-half).
// ---------------------------------------------------------------------------
#define WT_STRIDE 260
#define XS_STRIDE 132
#define GEMM_SMEM ((128 * WT_STRIDE + 128 * XS_STRIDE) * 4)

__global__ __launch_bounds__(512) void gemm_rest_kernel(
    const float* __restrict__ w,       // (3, 2, 256, 128)
    const float* __restrict__ bih,     // (4, 2, 256)
    const float* __restrict__ bhh,
    int layer, int insel)
{
    extern __shared__ float sm[];
    float* Wt  = sm;                       // [128][260]
    float* xst = sm + 128 * WT_STRIDE;     // [128][132]
    __shared__ float bsm[GG];

    const int b = blockIdx.x, dir = blockIdx.y, z = blockIdx.z;
    const int tid = threadIdx.x;
    const int gq = tid & 31;           // 32 gate-quads within half
    const int tq = (tid >> 5) & 7;     // 8 t-groups of 16
    const int gh = tid >> 8;           // gate half
    const int g0 = gh * 128 + 4 * gq;

    const float* wp = w + ((size_t)((layer - 1) * 2 + dir)) * GG * DH;
    for (int e = tid; e < GG * DH; e += 512) {
        int g = e >> 7, k = e & 127;
        Wt[k * WT_STRIDE + g] = wp[e];
    }
    if (tid < GG)
        bsm[tid] = bih[(layer * 2 + dir) * GG + tid] + bhh[(layer * 2 + dir) * GG + tid];

    const float* inb = g_hbuf[insel] + (size_t)b * TT * DH;
    float* outp = g_xw + ((size_t)(dir * BB + b)) * TT * GG;

    const int tbase = z * 500;
    const int tend  = tbase + 500;
    __syncthreads();

    for (int tc = tbase; tc < tend; tc += 128) {
        for (int e = tid; e < 128 * 128; e += 512) {
            int tt = e >> 7, d = e & 127;
            int t = tc + tt;
            xst[d * XS_STRIDE + tt] = (t < tend) ? inb[(size_t)t * DH + d] : 0.0f;
        }
        __syncthreads();

        u64 acc[4][8];
#pragma unroll
        for (int g = 0; g < 4; g++) {
            u64 bsp = splat2(bsm[g0 + g]);
#pragma unroll
            for (int tp = 0; tp < 8; tp++) acc[g][tp] = bsp;
        }

#pragma unroll 2
        for (int k = 0; k < 128; k++) {
            float4 w4 = *(const float4*)(Wt + k * WT_STRIDE + g0);
            const ulonglong2* xp =
                (const ulonglong2*)(xst + k * XS_STRIDE + tq * 16);
            ulonglong2 xA = xp[0], xB = xp[1], xC = xp[2], xD = xp[3];
            u64 x2[8] = {xA.x, xA.y, xB.x, xB.y, xC.x, xC.y, xD.x, xD.y};
            u64 ws[4] = {splat2(w4.x), splat2(w4.y), splat2(w4.z), splat2(w4.w)};
#pragma unroll
            for (int g = 0; g < 4; g++)
#pragma unroll
                for (int tp = 0; tp < 8; tp++)
                    acc[g][tp] = fma2(x2[tp], ws[g], acc[g][tp]);
        }

#pragma unroll
        for (int tp = 0; tp < 8; tp++) {
            float lo[4], hi[4];
#pragma unroll
            for (int g = 0; g < 4; g++) unpack2(acc[g][tp], lo[g], hi[g]);
            int t0 = tc + tq * 16 + 2 * tp;
            if (t0 < tend)
                *(float4*)(outp + (size_t)t0 * GG + g0) =
                    make_float4(lo[0], lo[1], lo[2], lo[3]);
            if (t0 + 1 < tend)
                *(float4*)(outp + (size_t)(t0 + 1) * GG + g0) =
                    make_float4(hi[0], hi[1], hi[2], hi[3]);
        }
        __syncthreads();
    }
}

// ---------------------------------------------------------------------------
// Recurrent scan v5 = v3 fma core + reduce-scatter/butterfly + dense acts.
// grid (B/4, 2), 512 threads, one barrier per step.
// Thread = (j, bp, ks): k-slice [16ks,16ks+16), batch pair {2bp,2bp+1}.
// After reduction each lane owns (batch 2bp+(ks&1), gate-half ks>>1):
// 2 activations/lane (dense MUFU), xor-16 exchange, redundant c.
// ---------------------------------------------------------------------------
#define HS_BSTRIDE 144   // floats per batch row (64 units * 2 dup + 4*4 pad)
#define HS_BUF     (4 * HS_BSTRIDE)

__global__ __launch_bounds__(512, 1) void lstm_recur_kernel(
    const float* __restrict__ whh,     // (4, 2, 256, 64)
    int layer, int outsel)
{
    __shared__ float hs2[2 * HS_BUF];  // double buffer

    const int dir = blockIdx.y;
    const int b0 = blockIdx.x * 4;
    const int tid = threadIdx.x;
    const int lane = tid & 31;
    const int j_lo = lane & 7;
    const int ks   = lane >> 3;          // k-slice 0..3
    const int wrp  = tid >> 5;
    const int j_hi = wrp & 7;
    const int bp   = wrp >> 3;           // batch pair 0..1
    const int j    = j_hi * 8 + j_lo;    // hidden unit 0..63
    const int bq   = ks & 1;             // owned batch-within-pair
    const int gh   = ks >> 1;            // owned gate half (0:(i,f) 1:(g,o))
    const int bwn  = 2 * bp + bq;        // owned local batch 0..3

    // W rows for the two gate pairs, k-slice only: 32 u64 regs
    u64 wp01[16], wp23[16];
    {
        const float* wb = whh + (size_t)(layer * 2 + dir) * GG * HH;
#pragma unroll
        for (int kk = 0; kk < 16; kk++) {
            int k = ks * 16 + kk;
            wp01[kk] = pack2(wb[(j)       * HH + k], wb[(64 + j)  * HH + k]);
            wp23[kk] = pack2(wb[(128 + j) * HH + k], wb[(192 + j) * HH + k]);
        }
    }

    for (int e = tid; e < 2 * HS_BUF; e += 512) hs2[e] = 0.0f;

    // activation constants for v0: tanh when gh==1 (gate g), sigmoid otherwise
    const float A0  = gh ? 2.0f : 1.0f;
    const float Bc0 = gh ? (-2.0f * L2E) : (-L2E);
    const float C0  = gh ? -1.0f : 0.0f;

    const float* xwp = g_xw + ((size_t)(dir * BB + b0 + bwn)) * TT * GG + gh * 128 + j;
    float* houtp = g_hbuf[outsel] + ((size_t)(b0 + bwn)) * TT * DH + dir * HH + j;
    float c = 0.0f;

    __syncthreads();

    // prefetch xw for step 0 (this lane's 2 gates)
    float nx0, nx1;
    {
        int t0 = dir ? (TT - 1) : 0;
        const float* xp = xwp + (size_t)t0 * GG;
        nx0 = xp[0]; nx1 = xp[64];
    }

    const int rdoff = (2 * bp) * HS_BSTRIDE + ks * 36;   // read base within buffer
    const int wroff = bwn * HS_BSTRIDE + (j >> 4) * 36 + (j & 15) * 2;

    for (int s = 0; s < TT; s++) {
        const int t = dir ? (TT - 1 - s) : s;
        float cx0 = nx0, cx1 = nx1;
        if (s + 1 < TT) {
            int tn = dir ? (t - 1) : (t + 1);
            const float* xp = xwp + (size_t)tn * GG;
            nx0 = xp[0]; nx1 = xp[64];
        }

        const float* h0p = hs2 + ((s + 1) & 1) * HS_BUF + rdoff;
        const float* h1p = h0p + HS_BSTRIDE;

        u64 z2 = pack2(0.f, 0.f);
        u64 a01_0 = z2, a23_0 = z2, a01_1 = z2, a23_1 = z2;
#pragma unroll
        for (int q = 0; q < 8; q++) {
            ulonglong2 hh0 = *(const ulonglong2*)(h0p + 4 * q);
            ulonglong2 hh1 = *(const ulonglong2*)(h1p + 4 * q);
            a01_0 = fma2(hh0.x, wp01[2 * q],     a01_0);
            a01_0 = fma2(hh0.y, wp01[2 * q + 1], a01_0);
            a23_0 = fma2(hh0.x, wp23[2 * q],     a23_0);
            a23_0 = fma2(hh0.y, wp23[2 * q + 1], a23_0);
            a01_1 = fma2(hh1.x, wp01[2 * q],     a01_1);
            a01_1 = fma2(hh1.y, wp01[2 * q + 1], a01_1);
            a23_1 = fma2(hh1.x, wp23[2 * q],     a23_1);
            a23_1 = fma2(hh1.y, wp23[2 * q + 1], a23_1);
        }

        // Round 1 (xor 8, batch bit): reduce-scatter by batch.
        u64 sA = bq ? a01_0 : a01_1;   // other-batch partials (sent)
        u64 sB = bq ? a23_0 : a23_1;
        u64 kA = bq ? a01_1 : a01_0;   // own-batch partials (kept)
        u64 kB = bq ? a23_1 : a23_0;
        u64 A01 = add2(kA, shfl2(sA, 8));
        u64 A23 = add2(kB, shfl2(sB, 8));

        // Round 2 (xor 16, k-slice-half bit): full butterfly on both pairs.
        A01 = add2(A01, shfl2(A01, 16));
        A23 = add2(A23, shfl2(A23, 16));
        // Now: fully k-reduced (i,f) in A01 and (g,o) in A23 for own batch.

        // Dense activations: this lane handles its gate-half pair only.
        u64 own = gh ? A23 : A01;
        float x0, x1; unpack2(own, x0, x1);
        x0 += cx0; x1 += cx1;
        float v0 = fmaf(A0, rcpa(1.0f + ex2a(Bc0 * x0)), C0); // sig(i) or tanh(g)
        float v1 = rcpa(1.0f + ex2a(-L2E * x1));              // sig(f) or sig(o)

        // exchange with the other gate-half (xor 16)
        u64 ov = shfl2(pack2(v0, v1), 16);
        float o0, o1; unpack2(ov, o0, o1);

        float gi = gh ? o0 : v0;
        float gf = gh ? o1 : v1;
        float gv = gh ? v0 : o0;
        float go = gh ? v1 : o1;

        c = fmaf(gf, c, gi * gv);
        float h = go * fast_tanh(c);

        if (ks < 2) {
            *(float2*)(hs2 + (s & 1) * HS_BUF + wroff) = make_float2(h, h);
        } else {
            houtp[(size_t)t * DH] = h;
        }
        __syncthreads();
    }
}

// ---------------------------------------------------------------------------
// Final linear head on last timestep of layer-3 output (g_hbuf[1]).
// ---------------------------------------------------------------------------
__global__ __launch_bounds__(64) void head_kernel(
    const float* __restrict__ wl,      // (54, 128)
    const float* __restrict__ bl,      // (54,)
    float* __restrict__ out)           // (B, 54)
{
    const int b = blockIdx.x;
    __shared__ float hsm[DH];
    const int tid = threadIdx.x;
    const float* hin = g_hbuf[1];
    for (int e = tid; e < DH; e += 64)
        hsm[e] = hin[((size_t)b * TT + (TT - 1)) * DH + e];
    __syncthreads();
    if (tid < 54) {
        float acc = bl[tid];
#pragma unroll
        for (int k = 0; k < DH; k++) acc = fmaf(hsm[k], wl[tid * DH + k], acc);
        out[b * 54 + tid] = acc;
    }
}

// ---------------------------------------------------------------------------
extern "C" void kernel_launch(void* const* d_in, const int* in_sizes, int n_in,
                              void* d_out, int out_size)
{
    (void)in_sizes; (void)n_in; (void)out_size;
    const float* x      = (const float*)d_in[0];
    const float* w_ih_f = (const float*)d_in[1];
    const float* w_ih_r = (const float*)d_in[2];
    const float* w_hh   = (const float*)d_in[3];
    const float* b_ih   = (const float*)d_in[4];
    const float* b_hh   = (const float*)d_in[5];
    const float* w_lin  = (const float*)d_in[6];
    const float* b_lin  = (const float*)d_in[7];
    float* out = (float*)d_out;

    cudaFuncSetAttribute(gemm_rest_kernel,
                         cudaFuncAttributeMaxDynamicSharedMemorySize, GEMM_SMEM);

    dim3 grid0(BB, 2);
    dim3 gridG(BB, 2, 2);
    dim3 gridR(BB / 4, 2);

    // Layer 0
    gemm0_kernel<<<grid0, 256>>>(x, w_ih_f, b_ih, b_hh);
    lstm_recur_kernel<<<gridR, 512>>>(w_hh, 0, 0);

    // Layers 1..3
    for (int l = 1; l < 4; l++) {
        gemm_rest_kernel<<<gridG, 512, GEMM_SMEM>>>(w_ih_r, b_ih, b_hh, l, (l - 1) & 1);
        lstm_recur_kernel<<<gridR, 512>>>(w_hh, l, l & 1);
    }

    // Head
    head_kernel<<<BB, 64>>>(w_lin, b_lin, out);
}

// round 6
// speedup vs baseline: 1.1897x; 1.1897x over previous
#include <cuda_runtime.h>
#include <math.h>

// Problem constants
#define BB   256
#define TT   1000
#define HH   64
#define GG   256   // 4*H
#define DIN  22
#define DH   128   // 2*H

// Scratch (device globals; no runtime allocation allowed)
__device__ float g_xw[(size_t)2 * BB * TT * GG];      // [dir][b][t][g]
__device__ float g_hT[2][(size_t)BB * DH * TT];       // transposed: [b][d][t]

typedef unsigned long long u64;

// ---- packed f32x2 helpers (FFMA2 pattern; exact fp32 math) ----
__device__ __forceinline__ u64 pack2(float lo, float hi) {
    u64 r; asm("mov.b64 %0, {%1, %2};" : "=l"(r) : "f"(lo), "f"(hi)); return r;
}
__device__ __forceinline__ void unpack2(u64 v, float& lo, float& hi) {
    asm("mov.b64 {%0, %1}, %2;" : "=f"(lo), "=f"(hi) : "l"(v));
}
__device__ __forceinline__ u64 splat2(float x) {
    u64 r; asm("mov.b64 %0, {%1, %1};" : "=l"(r) : "f"(x)); return r;
}
__device__ __forceinline__ u64 fma2(u64 a, u64 b, u64 c) {
    u64 d; asm("fma.rn.f32x2 %0, %1, %2, %3;" : "=l"(d) : "l"(a), "l"(b), "l"(c));
    return d;
}
// shuffle-xor both halves of a packed f32x2 and add
__device__ __forceinline__ u64 shfl_add2(u64 v, int m) {
    float lo, hi; unpack2(v, lo, hi);
    float lo2 = __shfl_xor_sync(0xFFFFFFFFu, lo, m);
    float hi2 = __shfl_xor_sync(0xFFFFFFFFu, hi, m);
    return pack2(lo + lo2, hi + hi2);
}

__device__ __forceinline__ float ex2a(float x) {
    float y; asm("ex2.approx.f32 %0, %1;" : "=f"(y) : "f"(x)); return y;
}
__device__ __forceinline__ float rcpa(float x) {
    float y; asm("rcp.approx.f32 %0, %1;" : "=f"(y) : "f"(x)); return y;
}

#define L2E  1.4426950408889634f

__device__ __forceinline__ float fast_sig(float x) {
    return rcpa(1.0f + ex2a(-L2E * x));
}
__device__ __forceinline__ float fast_tanh(float x) {
    return fmaf(2.0f, rcpa(1.0f + ex2a(-2.0f * L2E * x)), -1.0f);
}

// ---------------------------------------------------------------------------
// Layer-0 input projection (x is already t-contiguous)
// ---------------------------------------------------------------------------
__global__ __launch_bounds__(256) void gemm0_kernel(
    const float* __restrict__ x,       // (B, 22, T)
    const float* __restrict__ w,       // (2, 256, 22)
    const float* __restrict__ bih,     // (4, 2, 256)
    const float* __restrict__ bhh)     // (4, 2, 256)
{
    const int b = blockIdx.x, dir = blockIdx.y;
    const int g = threadIdx.x;
    __shared__ float xs[DIN][16];

    float wr[DIN];
#pragma unroll
    for (int d = 0; d < DIN; d++) wr[d] = w[(dir * GG + g) * DIN + d];
    const float bias = bih[dir * GG + g] + bhh[dir * GG + g];

    const float* xb = x + (size_t)b * DIN * TT;
    float* out = g_xw + ((size_t)(dir * BB + b)) * TT * GG;

    for (int tc = 0; tc < TT; tc += 16) {
        for (int e = threadIdx.x; e < DIN * 16; e += 256) {
            int d = e >> 4, tt = e & 15;
            int t = tc + tt;
            xs[d][tt] = (t < TT) ? xb[d * TT + t] : 0.0f;
        }
        __syncthreads();
        float acc[16];
#pragma unroll
        for (int tt = 0; tt < 16; tt++) acc[tt] = bias;
#pragma unroll
        for (int d = 0; d < DIN; d++) {
            float wd = wr[d];
#pragma unroll
            for (int tt = 0; tt < 16; tt++) acc[tt] = fmaf(wd, xs[d][tt], acc[tt]);
        }
#pragma unroll
        for (int tt = 0; tt < 16; tt++) {
            int t = tc + tt;
            if (t < TT) out[(size_t)t * GG + g] = acc[tt];
        }
        __syncthreads();
    }
}

// ---------------------------------------------------------------------------
// Layers 1..3 input projection, 256 threads, 2 blocks/SM.
// grid (B, 2, 2): (batch, dir, gate-half). Block covers 128 gates x all T.
// smem: Wt [128 k][132] (this half's gates) + xst [128 d][68] (64-t chunk,
// staged from the t-major g_hT so writes are conflict-free float4 along t).
// Thread tile: 4 gates x 8 timesteps.
// ---------------------------------------------------------------------------
#define GWS 132
#define GXS 68
#define GEMM_SMEM ((128 * GWS + 128 * GXS) * 4)   // 102400 B

__global__ __launch_bounds__(256, 2) void gemm_rest_kernel(
    const float* __restrict__ w,       // (3, 2, 256, 128)
    const float* __restrict__ bih,     // (4, 2, 256)
    const float* __restrict__ bhh,
    int layer, int insel)
{
    extern __shared__ float sm[];
    float* Wt  = sm;                   // [128][GWS]  (k-major, local gate cols)
    float* xst = sm + 128 * GWS;       // [128][GXS]  (d-major, tt cols)
    __shared__ float bsm[128];

    const int b = blockIdx.x, dir = blockIdx.y, gh = blockIdx.z;
    const int tid = threadIdx.x;
    const int gq = tid & 31;           // gate quad within half
    const int tq = tid >> 5;           // 0..7 (8 t per thread)
    const int gl0 = 4 * gq;            // local gate base
    const int g0 = gh * 128 + gl0;     // global gate base

    // Stage W transposed (one-time): Wt[k][gl] = W[gh*128+gl][k]
    const float* wp = w + ((size_t)((layer - 1) * 2 + dir)) * GG * DH
                        + (size_t)gh * 128 * DH;
    for (int e = tid; e < 128 * DH; e += 256) {
        int g = e >> 7, k = e & 127;
        Wt[k * GWS + g] = wp[e];
    }
    if (tid < 128)
        bsm[tid] = bih[(layer * 2 + dir) * GG + gh * 128 + tid]
                 + bhh[(layer * 2 + dir) * GG + gh * 128 + tid];

    const float* inT = g_hT[insel] + (size_t)b * DH * TT;  // [d][t]
    float* outp = g_xw + ((size_t)(dir * BB + b)) * TT * GG;
    __syncthreads();

    for (int tc = 0; tc < TT; tc += 64) {
        // Stage x chunk: xst[d][tt] = inT[d][tc+tt], float4 along t
        for (int f = tid; f < 128 * 16; f += 256) {
            int d = f >> 4, t4 = f & 15;
            int tg = tc + 4 * t4;
            float4 v = (tg + 3 < TT)
                ? *(const float4*)(inT + (size_t)d * TT + tg)
                : make_float4(0.f, 0.f, 0.f, 0.f);
            *(float4*)(xst + d * GXS + 4 * t4) = v;
        }
        __syncthreads();

        u64 acc[4][4];
#pragma unroll
        for (int g = 0; g < 4; g++) {
            u64 bsp = splat2(bsm[gl0 + g]);
#pragma unroll
            for (int tp = 0; tp < 4; tp++) acc[g][tp] = bsp;
        }

#pragma unroll 8
        for (int k = 0; k < 128; k++) {
            float4 w4 = *(const float4*)(Wt + k * GWS + gl0);
            const ulonglong2* xp = (const ulonglong2*)(xst + k * GXS + tq * 8);
            ulonglong2 xA = xp[0], xB = xp[1];
            u64 x2[4] = {xA.x, xA.y, xB.x, xB.y};
            u64 ws[4] = {splat2(w4.x), splat2(w4.y), splat2(w4.z), splat2(w4.w)};
#pragma unroll
            for (int g = 0; g < 4; g++)
#pragma unroll
                for (int tp = 0; tp < 4; tp++)
                    acc[g][tp] = fma2(x2[tp], ws[g], acc[g][tp]);
        }

#pragma unroll
        for (int tp = 0; tp < 4; tp++) {
            float lo[4], hi[4];
#pragma unroll
            for (int g = 0; g < 4; g++) unpack2(acc[g][tp], lo[g], hi[g]);
            int t0 = tc + tq * 8 + 2 * tp;
            if (t0 < TT) {
                *(float4*)(outp + (size_t)t0 * GG + g0) =
                    make_float4(lo[0], lo[1], lo[2], lo[3]);
                *(float4*)(outp + (size_t)(t0 + 1) * GG + g0) =
                    make_float4(hi[0], hi[1], hi[2], hi[3]);
            }
        }
        __syncthreads();
    }
}

// ---------------------------------------------------------------------------
// Recurrent scan (v3 structure, 256 threads, 2 batches/block, 2 blocks/SM).
// Thread = (j 0..63, ks 0..3): gates 2 pairs for unit j, both block batches,
// k-slice [16ks,16ks+16). W in regs, full butterfly reduction (xor 8,16),
// act lanes (ks<2) own batch ks and do the cell update. One barrier/step.
// ---------------------------------------------------------------------------
#define HS_BSTRIDE 144   // floats per batch row (64 units * 2 dup + 4*4 pad)
#define HS_BUF     (2 * HS_BSTRIDE)

__global__ __launch_bounds__(256, 2) void lstm_recur_kernel(
    const float* __restrict__ whh,     // (4, 2, 256, 64)
    int layer, int outsel)
{
    __shared__ float hs2[2 * HS_BUF];  // double buffer

    const int dir = blockIdx.y;
    const int b0 = blockIdx.x * 2;
    const int tid = threadIdx.x;
    const int lane = tid & 31;
    const int j_lo = lane & 7;
    const int ks   = lane >> 3;          // k-slice 0..3
    const int j_hi = tid >> 5;           // warp 0..7
    const int j    = j_hi * 8 + j_lo;    // hidden unit 0..63

    // W rows for the two gate pairs, this k-slice: 32 u64 regs
    u64 wp01[16], wp23[16];
    {
        const float* wb = whh + (size_t)(layer * 2 + dir) * GG * HH;
#pragma unroll
        for (int kk = 0; kk < 16; kk++) {
            int k = ks * 16 + kk;
            wp01[kk] = pack2(wb[(j)       * HH + k], wb[(64 + j)  * HH + k]);
            wp23[kk] = pack2(wb[(128 + j) * HH + k], wb[(192 + j) * HH + k]);
        }
    }

    for (int e = tid; e < 2 * HS_BUF; e += 256) hs2[e] = 0.0f;

    const bool act = (ks < 2);
    const int bl = ks & 1;               // owned local batch (if act)
    const float* xwp = g_xw + ((size_t)(dir * BB + b0 + bl)) * TT * GG + j;
    float* houtTp = g_hT[outsel] + ((size_t)(b0 + bl) * DH + dir * HH + j) * TT;
    float c = 0.0f;

    __syncthreads();

    // prefetch xw for step 0
    float nx_i = 0.f, nx_f = 0.f, nx_g = 0.f, nx_o = 0.f;
    if (act) {
        int t0 = dir ? (TT - 1) : 0;
        const float* xp = xwp + (size_t)t0 * GG;
        nx_i = xp[0]; nx_f = xp[64]; nx_g = xp[128]; nx_o = xp[192];
    }

    const int rdoff = ks * 36;           // k-slice offset within a batch row
    const int wroff = bl * HS_BSTRIDE + (j >> 4) * 36 + (j & 15) * 2;

    for (int s = 0; s < TT; s++) {
        const int t = dir ? (TT - 1 - s) : s;
        float cx_i = nx_i, cx_f = nx_f, cx_g = nx_g, cx_o = nx_o;
        if (act && s + 1 < TT) {
            int tn = dir ? (t - 1) : (t + 1);
            const float* xp = xwp + (size_t)tn * GG;
            nx_i = xp[0]; nx_f = xp[64]; nx_g = xp[128]; nx_o = xp[192];
        }

        const float* h0p = hs2 + ((s + 1) & 1) * HS_BUF + rdoff;   // batch 0
        const float* h1p = h0p + HS_BSTRIDE;                        // batch 1

        u64 z2 = pack2(0.f, 0.f);
        u64 a01_0 = z2, a23_0 = z2, a01_1 = z2, a23_1 = z2;
#pragma unroll
        for (int q = 0; q < 8; q++) {
            ulonglong2 hh0 = *(const ulonglong2*)(h0p + 4 * q);
            ulonglong2 hh1 = *(const ulonglong2*)(h1p + 4 * q);
            a01_0 = fma2(hh0.x, wp01[2 * q],     a01_0);
            a01_0 = fma2(hh0.y, wp01[2 * q + 1], a01_0);
            a23_0 = fma2(hh0.x, wp23[2 * q],     a23_0);
            a23_0 = fma2(hh0.y, wp23[2 * q + 1], a23_0);
            a01_1 = fma2(hh1.x, wp01[2 * q],     a01_1);
            a01_1 = fma2(hh1.y, wp01[2 * q + 1], a01_1);
            a23_1 = fma2(hh1.x, wp23[2 * q],     a23_1);
            a23_1 = fma2(hh1.y, wp23[2 * q + 1], a23_1);
        }

        // full butterfly over the 4 k-slices (independent chains)
        a01_0 = shfl_add2(a01_0, 8); a01_0 = shfl_add2(a01_0, 16);
        a23_0 = shfl_add2(a23_0, 8); a23_0 = shfl_add2(a23_0, 16);
        a01_1 = shfl_add2(a01_1, 8); a01_1 = shfl_add2(a01_1, 16);
        a23_1 = shfl_add2(a23_1, 8); a23_1 = shfl_add2(a23_1, 16);

        if (act) {
            u64 a01 = bl ? a01_1 : a01_0;
            u64 a23 = bl ? a23_1 : a23_0;
            float ai, af, ag, ao;
            unpack2(a01, ai, af);
            unpack2(a23, ag, ao);
            ai += cx_i; af += cx_f; ag += cx_g; ao += cx_o;
            float gi = fast_sig(ai);
            float gf = fast_sig(af);
            float gv = fast_tanh(ag);
            float go = fast_sig(ao);
            c = fmaf(gf, c, gi * gv);
            float h = go * fast_tanh(c);
            *(float2*)(hs2 + (s & 1) * HS_BUF + wroff) = make_float2(h, h);
            houtTp[t] = h;
        }
        __syncthreads();
    }
}

// ---------------------------------------------------------------------------
// Final linear head on last timestep of layer-3 output (g_hT[1]).
// ---------------------------------------------------------------------------
__global__ __launch_bounds__(64) void head_kernel(
    const float* __restrict__ wl,      // (54, 128)
    const float* __restrict__ bl,      // (54,)
    float* __restrict__ out)           // (B, 54)
{
    const int b = blockIdx.x;
    __shared__ float hsm[DH];
    const int tid = threadIdx.x;
    const float* hin = g_hT[1];
    for (int e = tid; e < DH; e += 64)
        hsm[e] = hin[((size_t)b * DH + e) * TT + (TT - 1)];
    __syncthreads();
    if (tid < 54) {
        float acc = bl[tid];
#pragma unroll
        for (int k = 0; k < DH; k++) acc = fmaf(hsm[k], wl[tid * DH + k], acc);
        out[b * 54 + tid] = acc;
    }
}

// ---------------------------------------------------------------------------
extern "C" void kernel_launch(void* const* d_in, const int* in_sizes, int n_in,
                              void* d_out, int out_size)
{
    (void)in_sizes; (void)n_in; (void)out_size;
    const float* x      = (const float*)d_in[0];
    const float* w_ih_f = (const float*)d_in[1];
    const float* w_ih_r = (const float*)d_in[2];
    const float* w_hh   = (const float*)d_in[3];
    const float* b_ih   = (const float*)d_in[4];
    const float* b_hh   = (const float*)d_in[5];
    const float* w_lin  = (const float*)d_in[6];
    const float* b_lin  = (const float*)d_in[7];
    float* out = (float*)d_out;

    cudaFuncSetAttribute(gemm_rest_kernel,
                         cudaFuncAttributeMaxDynamicSharedMemorySize, GEMM_SMEM);

    dim3 grid0(BB, 2);
    dim3 gridG(BB, 2, 2);     // (batch, dir, gate-half)
    dim3 gridR(BB / 2, 2);    // 256 blocks, 2 batches each

    // Layer 0
    gemm0_kernel<<<grid0, 256>>>(x, w_ih_f, b_ih, b_hh);
    lstm_recur_kernel<<<gridR, 256>>>(w_hh, 0, 0);

    // Layers 1..3
    for (int l = 1; l < 4; l++) {
        gemm_rest_kernel<<<gridG, 256, GEMM_SMEM>>>(w_ih_r, b_ih, b_hh, l, (l - 1) & 1);
        lstm_recur_kernel<<<gridR, 256>>>(w_hh, l, l & 1);
    }

    // Head
    head_kernel<<<BB, 64>>>(w_lin, b_lin, out);
}

// round 8
// speedup vs baseline: 1.2771x; 1.0734x over previous
#include <cuda_runtime.h>
#include <math.h>

// Problem constants
#define BB   256
#define TT   1000
#define HH   64
#define GG   256   // 4*H
#define DIN  22
#define DH   128   // 2*H

// Scratch (device globals; no runtime allocation allowed)
__device__ float g_xw[(size_t)2 * BB * TT * GG];      // [dir][b][t][g]
__device__ float g_hT[2][(size_t)BB * DH * TT];       // transposed: [b][d][t]

typedef unsigned long long u64;

// ---- packed f32x2 helpers (FFMA2 pattern; exact fp32 math) ----
__device__ __forceinline__ u64 pack2(float lo, float hi) {
    u64 r; asm("mov.b64 %0, {%1, %2};" : "=l"(r) : "f"(lo), "f"(hi)); return r;
}
__device__ __forceinline__ void unpack2(u64 v, float& lo, float& hi) {
    asm("mov.b64 {%0, %1}, %2;" : "=f"(lo), "=f"(hi) : "l"(v));
}
__device__ __forceinline__ u64 splat2(float x) {
    u64 r; asm("mov.b64 %0, {%1, %1};" : "=l"(r) : "f"(x)); return r;
}
__device__ __forceinline__ u64 fma2(u64 a, u64 b, u64 c) {
    u64 d; asm("fma.rn.f32x2 %0, %1, %2, %3;" : "=l"(d) : "l"(a), "l"(b), "l"(c));
    return d;
}
// shuffle-xor both halves of a packed f32x2 and add
__device__ __forceinline__ u64 shfl_add2(u64 v, int m) {
    float lo, hi; unpack2(v, lo, hi);
    float lo2 = __shfl_xor_sync(0xFFFFFFFFu, lo, m);
    float hi2 = __shfl_xor_sync(0xFFFFFFFFu, hi, m);
    return pack2(lo + lo2, hi + hi2);
}

__device__ __forceinline__ float ex2a(float x) {
    float y; asm("ex2.approx.f32 %0, %1;" : "=f"(y) : "f"(x)); return y;
}
__device__ __forceinline__ float rcpa(float x) {
    float y; asm("rcp.approx.f32 %0, %1;" : "=f"(y) : "f"(x)); return y;
}

#define L2E  1.4426950408889634f

__device__ __forceinline__ float fast_sig(float x) {
    return rcpa(1.0f + ex2a(-L2E * x));
}
__device__ __forceinline__ float fast_tanh(float x) {
    return fmaf(2.0f, rcpa(1.0f + ex2a(-2.0f * L2E * x)), -1.0f);
}

// ---------------------------------------------------------------------------
// Layer-0 input projection (x is already t-contiguous)
// ---------------------------------------------------------------------------
__global__ __launch_bounds__(256) void gemm0_kernel(
    const float* __restrict__ x,       // (B, 22, T)
    const float* __restrict__ w,       // (2, 256, 22)
    const float* __restrict__ bih,     // (4, 2, 256)
    const float* __restrict__ bhh)     // (4, 2, 256)
{
    const int b = blockIdx.x, dir = blockIdx.y;
    const int g = threadIdx.x;
    __shared__ float xs[DIN][16];

    float wr[DIN];
#pragma unroll
    for (int d = 0; d < DIN; d++) wr[d] = w[(dir * GG + g) * DIN + d];
    const float bias = bih[dir * GG + g] + bhh[dir * GG + g];

    const float* xb = x + (size_t)b * DIN * TT;
    float* out = g_xw + ((size_t)(dir * BB + b)) * TT * GG;

    for (int tc = 0; tc < TT; tc += 16) {
        for (int e = threadIdx.x; e < DIN * 16; e += 256) {
            int d = e >> 4, tt = e & 15;
            int t = tc + tt;
            xs[d][tt] = (t < TT) ? xb[d * TT + t] : 0.0f;
        }
        __syncthreads();
        float acc[16];
#pragma unroll
        for (int tt = 0; tt < 16; tt++) acc[tt] = bias;
#pragma unroll
        for (int d = 0; d < DIN; d++) {
            float wd = wr[d];
#pragma unroll
            for (int tt = 0; tt < 16; tt++) acc[tt] = fmaf(wd, xs[d][tt], acc[tt]);
        }
#pragma unroll
        for (int tt = 0; tt < 16; tt++) {
            int t = tc + tt;
            if (t < TT) out[(size_t)t * GG + g] = acc[tt];
        }
        __syncthreads();
    }
}

// ---------------------------------------------------------------------------
// Layers 1..3 input projection, 256 threads, 2 blocks/SM.
// grid (B, 2, 8): z = gh + 2*tchunk; tchunk covers 256 t (last: 232).
// tbase is a multiple of 64 -> all float4 staging loads 16B-aligned.
// smem: Wt [128 k][132] + xst [128 d][68]. Thread tile: 4 gates x 8 t.
// ---------------------------------------------------------------------------
#define GWS 132
#define GXS 68
#define GEMM_SMEM ((128 * GWS + 128 * GXS) * 4)   // 102400 B

__global__ __launch_bounds__(256, 2) void gemm_rest_kernel(
    const float* __restrict__ w,       // (3, 2, 256, 128)
    const float* __restrict__ bih,     // (4, 2, 256)
    const float* __restrict__ bhh,
    int layer, int insel)
{
    extern __shared__ float sm[];
    float* Wt  = sm;                   // [128][GWS]  (k-major, local gate cols)
    float* xst = sm + 128 * GWS;       // [128][GXS]  (d-major, tt cols)
    __shared__ float bsm[128];

    const int b = blockIdx.x, dir = blockIdx.y;
    const int gh = blockIdx.z & 1;
    const int tch = blockIdx.z >> 1;   // 0..3
    const int tid = threadIdx.x;
    const int gq = tid & 31;           // gate quad within half
    const int tq = tid >> 5;           // 0..7 (8 t per thread)
    const int gl0 = 4 * gq;            // local gate base
    const int g0 = gh * 128 + gl0;     // global gate base

    // Stage W transposed (one-time): Wt[k][gl] = W[gh*128+gl][k]
    const float* wp = w + ((size_t)((layer - 1) * 2 + dir)) * GG * DH
                        + (size_t)gh * 128 * DH;
    for (int e = tid; e < 128 * DH; e += 256) {
        int g = e >> 7, k = e & 127;
        Wt[k * GWS + g] = wp[e];
    }
    if (tid < 128)
        bsm[tid] = bih[(layer * 2 + dir) * GG + gh * 128 + tid]
                 + bhh[(layer * 2 + dir) * GG + gh * 128 + tid];

    const float* inT = g_hT[insel] + (size_t)b * DH * TT;  // [d][t]
    float* outp = g_xw + ((size_t)(dir * BB + b)) * TT * GG;

    const int tbase = tch * 256;                   // multiple of 64 (aligned)
    const int tend  = (tbase + 256 < TT) ? (tbase + 256) : TT;
    __syncthreads();

    for (int tc = tbase; tc < tend; tc += 64) {
        // Stage x chunk: xst[d][tt] = inT[d][tc+tt], float4 along t (aligned)
        for (int f = tid; f < 128 * 16; f += 256) {
            int d = f >> 4, t4 = f & 15;
            int tg = tc + 4 * t4;
            float4 v = (tg + 3 < TT)
                ? *(const float4*)(inT + (size_t)d * TT + tg)
                : make_float4(0.f, 0.f, 0.f, 0.f);
            *(float4*)(xst + d * GXS + 4 * t4) = v;
        }
        __syncthreads();

        u64 acc[4][4];
#pragma unroll
        for (int g = 0; g < 4; g++) {
            u64 bsp = splat2(bsm[gl0 + g]);
#pragma unroll
            for (int tp = 0; tp < 4; tp++) acc[g][tp] = bsp;
        }

#pragma unroll 8
        for (int k = 0; k < 128; k++) {
            float4 w4 = *(const float4*)(Wt + k * GWS + gl0);
            const ulonglong2* xp = (const ulonglong2*)(xst + k * GXS + tq * 8);
            ulonglong2 xA = xp[0], xB = xp[1];
            u64 x2[4] = {xA.x, xA.y, xB.x, xB.y};
            u64 ws[4] = {splat2(w4.x), splat2(w4.y), splat2(w4.z), splat2(w4.w)};
#pragma unroll
            for (int g = 0; g < 4; g++)
#pragma unroll
                for (int tp = 0; tp < 4; tp++)
                    acc[g][tp] = fma2(x2[tp], ws[g], acc[g][tp]);
        }

#pragma unroll
        for (int tp = 0; tp < 4; tp++) {
            float lo[4], hi[4];
#pragma unroll
            for (int g = 0; g < 4; g++) unpack2(acc[g][tp], lo[g], hi[g]);
            int t0 = tc + tq * 8 + 2 * tp;
            if (t0 < tend)
                *(float4*)(outp + (size_t)t0 * GG + g0) =
                    make_float4(lo[0], lo[1], lo[2], lo[3]);
            if (t0 + 1 < tend)
                *(float4*)(outp + (size_t)(t0 + 1) * GG + g0) =
                    make_float4(hi[0], hi[1], hi[2], hi[3]);
        }
        __syncthreads();
    }
}

// ---------------------------------------------------------------------------
// Recurrent scan v7: v6 reduction/tail + k-pair-packed h loads (non-dup smem,
// 8 LDS.128/thread/step instead of 16; 8 independent acc chains).
// grid (B/2, 2), 256 threads, 2 blocks/SM, one barrier per step.
// Thread = (j 0..63, ks 0..3): 4 gates for unit j, both block batches,
// k-slice [16ks,16ks+16). Butterfly reduction (xor 8,16) on packed pairs;
// act lanes (ks<2) own batch ks and do the cell update.
// h smem row = 4 groups of (16 units + 4 pad) = 80 floats (ks bank-disjoint;
// every 16B-group start is 16B-aligned).
// ---------------------------------------------------------------------------
#define HROW 80
#define HBUF (2 * HROW)

__global__ __launch_bounds__(256, 2) void lstm_recur_kernel(
    const float* __restrict__ whh,     // (4, 2, 256, 64)
    int layer, int outsel)
{
    __shared__ __align__(16) float hs2[2 * HBUF];    // double buffer

    const int dir = blockIdx.y;
    const int b0 = blockIdx.x * 2;
    const int tid = threadIdx.x;
    const int lane = tid & 31;
    const int j_lo = lane & 7;
    const int ks   = lane >> 3;          // k-slice 0..3
    const int j_hi = tid >> 5;           // warp 0..7
    const int j    = j_hi * 8 + j_lo;    // hidden unit 0..63

    // W rows for 4 gates, k-pair packed, this k-slice: 32 u64 regs
    u64 wg[4][8];
    {
        const float* wb = whh + (size_t)(layer * 2 + dir) * GG * HH;
#pragma unroll
        for (int g = 0; g < 4; g++) {
            const float2* wr = (const float2*)(wb + ((size_t)(g * 64 + j)) * HH + ks * 16);
#pragma unroll
            for (int p = 0; p < 8; p++) {
                float2 v = wr[p];
                wg[g][p] = pack2(v.x, v.y);
            }
        }
    }

    for (int e = tid; e < 2 * HBUF; e += 256) hs2[e] = 0.0f;

    const bool act = (ks < 2);
    const int bl = ks & 1;               // owned local batch (if act)
    const float* xwp = g_xw + ((size_t)(dir * BB + b0 + bl)) * TT * GG + j;
    float* houtTp = g_hT[outsel] + ((size_t)(b0 + bl) * DH + dir * HH + j) * TT;
    float c = 0.0f;

    __syncthreads();

    // prefetch xw for step 0
    float nx_i = 0.f, nx_f = 0.f, nx_g = 0.f, nx_o = 0.f;
    if (act) {
        int t0 = dir ? (TT - 1) : 0;
        const float* xp = xwp + (size_t)t0 * GG;
        nx_i = xp[0]; nx_f = xp[64]; nx_g = xp[128]; nx_o = xp[192];
    }

    const int rdoff = ks * 20;                       // k-slice offset in row
    const int wroff = bl * HROW + (j >> 4) * 20 + (j & 15);

    for (int s = 0; s < TT; s++) {
        const int t = dir ? (TT - 1 - s) : s;
        float cx_i = nx_i, cx_f = nx_f, cx_g = nx_g, cx_o = nx_o;
        if (act && s + 1 < TT) {
            int tn = dir ? (t - 1) : (t + 1);
            const float* xp = xwp + (size_t)tn * GG;
            nx_i = xp[0]; nx_f = xp[64]; nx_g = xp[128]; nx_o = xp[192];
        }

        const float* hb = hs2 + ((s + 1) & 1) * HBUF + rdoff;
        const ulonglong2* h0p = (const ulonglong2*)hb;          // batch 0
        const ulonglong2* h1p = (const ulonglong2*)(hb + HROW); // batch 1

        u64 z = pack2(0.f, 0.f);
        u64 acc[4][2];
#pragma unroll
        for (int g = 0; g < 4; g++) { acc[g][0] = z; acc[g][1] = z; }

#pragma unroll
        for (int q = 0; q < 4; q++) {
            ulonglong2 h0 = h0p[q];   // k-pairs 2q, 2q+1 of batch 0
            ulonglong2 h1 = h1p[q];
#pragma unroll
            for (int g = 0; g < 4; g++) {
                acc[g][0] = fma2(h0.x, wg[g][2 * q],     acc[g][0]);
                acc[g][0] = fma2(h0.y, wg[g][2 * q + 1], acc[g][0]);
                acc[g][1] = fma2(h1.x, wg[g][2 * q],     acc[g][1]);
                acc[g][1] = fma2(h1.y, wg[g][2 * q + 1], acc[g][1]);
            }
        }

        // horizontal k-pair add -> 8 scalars, then pack by (gate-pair, batch)
        float sv[4][2];
#pragma unroll
        for (int g = 0; g < 4; g++)
#pragma unroll
            for (int bb = 0; bb < 2; bb++) {
                float lo, hi; unpack2(acc[g][bb], lo, hi);
                sv[g][bb] = lo + hi;
            }
        u64 P0 = pack2(sv[0][0], sv[1][0]);  // (i,f) batch0
        u64 Q0 = pack2(sv[2][0], sv[3][0]);  // (g,o) batch0
        u64 P1 = pack2(sv[0][1], sv[1][1]);
        u64 Q1 = pack2(sv[2][1], sv[3][1]);

        // full butterfly over the 4 k-slices (independent chains)
        P0 = shfl_add2(P0, 8); P0 = shfl_add2(P0, 16);
        Q0 = shfl_add2(Q0, 8); Q0 = shfl_add2(Q0, 16);
        P1 = shfl_add2(P1, 8); P1 = shfl_add2(P1, 16);
        Q1 = shfl_add2(Q1, 8); Q1 = shfl_add2(Q1, 16);

        if (act) {
            u64 a01 = bl ? P1 : P0;
            u64 a23 = bl ? Q1 : Q0;
            float ai, af, ag, ao;
            unpack2(a01, ai, af);
            unpack2(a23, ag, ao);
            ai += cx_i; af += cx_f; ag += cx_g; ao += cx_o;
            float gi = fast_sig(ai);
            float gf = fast_sig(af);
            float gv = fast_tanh(ag);
            float go = fast_sig(ao);
            c = fmaf(gf, c, gi * gv);
            float h = go * fast_tanh(c);
            hs2[(s & 1) * HBUF + wroff] = h;
            houtTp[t] = h;
        }
        __syncthreads();
    }
}

// ---------------------------------------------------------------------------
// Final linear head on last timestep of layer-3 output (g_hT[1]).
// ---------------------------------------------------------------------------
__global__ __launch_bounds__(64) void head_kernel(
    const float* __restrict__ wl,      // (54, 128)
    const float* __restrict__ bl,      // (54,)
    float* __restrict__ out)           // (B, 54)
{
    const int b = blockIdx.x;
    __shared__ float hsm[DH];
    const int tid = threadIdx.x;
    const float* hin = g_hT[1];
    for (int e = tid; e < DH; e += 64)
        hsm[e] = hin[((size_t)b * DH + e) * TT + (TT - 1)];
    __syncthreads();
    if (tid < 54) {
        float acc = bl[tid];
#pragma unroll
        for (int k = 0; k < DH; k++) acc = fmaf(hsm[k], wl[tid * DH + k], acc);
        out[b * 54 + tid] = acc;
    }
}

// ---------------------------------------------------------------------------
extern "C" void kernel_launch(void* const* d_in, const int* in_sizes, int n_in,
                              void* d_out, int out_size)
{
    (void)in_sizes; (void)n_in; (void)out_size;
    const float* x      = (const float*)d_in[0];
    const float* w_ih_f = (const float*)d_in[1];
    const float* w_ih_r = (const float*)d_in[2];
    const float* w_hh   = (const float*)d_in[3];
    const float* b_ih   = (const float*)d_in[4];
    const float* b_hh   = (const float*)d_in[5];
    const float* w_lin  = (const float*)d_in[6];
    const float* b_lin  = (const float*)d_in[7];
    float* out = (float*)d_out;

    cudaFuncSetAttribute(gemm_rest_kernel,
                         cudaFuncAttributeMaxDynamicSharedMemorySize, GEMM_SMEM);

    dim3 grid0(BB, 2);
    dim3 gridG(BB, 2, 8);     // (batch, dir, gh + 2*tchunk)
    dim3 gridR(BB / 2, 2);    // 256 blocks, 2 batches each

    // Layer 0
    gemm0_kernel<<<grid0, 256>>>(x, w_ih_f, b_ih, b_hh);
    lstm_recur_kernel<<<gridR, 256>>>(w_hh, 0, 0);

    // Layers 1..3
    for (int l = 1; l < 4; l++) {
        gemm_rest_kernel<<<gridG, 256, GEMM_SMEM>>>(w_ih_r, b_ih, b_hh, l, (l - 1) & 1);
        lstm_recur_kernel<<<gridR, 256>>>(w_hh, l, l & 1);
    }

    // Head
    head_kernel<<<BB, 64>>>(w_lin, b_lin, out);
}

// round 9
// speedup vs baseline: 1.3004x; 1.0183x over previous
#include <cuda_runtime.h>
#include <math.h>

// Problem constants
#define BB   256
#define TT   1000
#define HH   64
#define GG   256   // 4*H
#define DIN  22
#define DH   128   // 2*H

// Scratch (device globals; no runtime allocation allowed)
__device__ float g_xw[(size_t)2 * BB * TT * GG];      // [dir][b][t][g]
__device__ float g_hT[2][(size_t)BB * DH * TT];       // transposed: [b][d][t]

typedef unsigned long long u64;

// ---- packed f32x2 helpers (FFMA2 pattern; exact fp32 math) ----
__device__ __forceinline__ u64 pack2(float lo, float hi) {
    u64 r; asm("mov.b64 %0, {%1, %2};" : "=l"(r) : "f"(lo), "f"(hi)); return r;
}
__device__ __forceinline__ void unpack2(u64 v, float& lo, float& hi) {
    asm("mov.b64 {%0, %1}, %2;" : "=f"(lo), "=f"(hi) : "l"(v));
}
__device__ __forceinline__ u64 splat2(float x) {
    u64 r; asm("mov.b64 %0, {%1, %1};" : "=l"(r) : "f"(x)); return r;
}
__device__ __forceinline__ u64 fma2(u64 a, u64 b, u64 c) {
    u64 d; asm("fma.rn.f32x2 %0, %1, %2, %3;" : "=l"(d) : "l"(a), "l"(b), "l"(c));
    return d;
}
// shuffle-xor both halves of a packed f32x2 and add
__device__ __forceinline__ u64 shfl_add2(u64 v, int m) {
    float lo, hi; unpack2(v, lo, hi);
    float lo2 = __shfl_xor_sync(0xFFFFFFFFu, lo, m);
    float hi2 = __shfl_xor_sync(0xFFFFFFFFu, hi, m);
    return pack2(lo + lo2, hi + hi2);
}

__device__ __forceinline__ float ex2a(float x) {
    float y; asm("ex2.approx.f32 %0, %1;" : "=f"(y) : "f"(x)); return y;
}
__device__ __forceinline__ float rcpa(float x) {
    float y; asm("rcp.approx.f32 %0, %1;" : "=f"(y) : "f"(x)); return y;
}

#define L2E  1.4426950408889634f

__device__ __forceinline__ float fast_sig(float x) {
    return rcpa(1.0f + ex2a(-L2E * x));
}
__device__ __forceinline__ float fast_tanh(float x) {
    return fmaf(2.0f, rcpa(1.0f + ex2a(-2.0f * L2E * x)), -1.0f);
}

// ---------------------------------------------------------------------------
// Layer-0 input projection, t-split x4. grid (B, 2, 4), 256 threads.
// ---------------------------------------------------------------------------
__global__ __launch_bounds__(256) void gemm0_kernel(
    const float* __restrict__ x,       // (B, 22, T)
    const float* __restrict__ w,       // (2, 256, 22)
    const float* __restrict__ bih,     // (4, 2, 256)
    const float* __restrict__ bhh)     // (4, 2, 256)
{
    const int b = blockIdx.x, dir = blockIdx.y, tch = blockIdx.z;
    const int g = threadIdx.x;
    __shared__ float xs[DIN][16];

    float wr[DIN];
#pragma unroll
    for (int d = 0; d < DIN; d++) wr[d] = w[(dir * GG + g) * DIN + d];
    const float bias = bih[dir * GG + g] + bhh[dir * GG + g];

    const float* xb = x + (size_t)b * DIN * TT;
    float* out = g_xw + ((size_t)(dir * BB + b)) * TT * GG;

    const int tbase = tch * 256;
    const int tend  = (tbase + 256 < TT) ? (tbase + 256) : TT;

    for (int tc = tbase; tc < tend; tc += 16) {
        for (int e = threadIdx.x; e < DIN * 16; e += 256) {
            int d = e >> 4, tt = e & 15;
            int t = tc + tt;
            xs[d][tt] = (t < TT) ? xb[d * TT + t] : 0.0f;
        }
        __syncthreads();
        float acc[16];
#pragma unroll
        for (int tt = 0; tt < 16; tt++) acc[tt] = bias;
#pragma unroll
        for (int d = 0; d < DIN; d++) {
            float wd = wr[d];
#pragma unroll
            for (int tt = 0; tt < 16; tt++) acc[tt] = fmaf(wd, xs[d][tt], acc[tt]);
        }
#pragma unroll
        for (int tt = 0; tt < 16; tt++) {
            int t = tc + tt;
            if (t < tend) out[(size_t)t * GG + g] = acc[tt];
        }
        __syncthreads();
    }
}

// ---------------------------------------------------------------------------
// Layers 1..3 input projection, 256 threads, 2 blocks/SM.
// grid (B, 2, 8): z = gh + 2*tchunk; tchunk covers 256 t (last: 232).
// Register-prefetch pipeline: tile i+1's 8 float4 staging loads are issued
// before computing tile i; stored to smem after the compute barrier.
// smem: Wt [128 k][132] + xst [128 d][68]. Thread tile: 4 gates x 8 t.
// ---------------------------------------------------------------------------
#define GWS 132
#define GXS 68
#define GEMM_SMEM ((128 * GWS + 128 * GXS) * 4)   // 102400 B

__global__ __launch_bounds__(256, 2) void gemm_rest_kernel(
    const float* __restrict__ w,       // (3, 2, 256, 128)
    const float* __restrict__ bih,     // (4, 2, 256)
    const float* __restrict__ bhh,
    int layer, int insel)
{
    extern __shared__ float sm[];
    float* Wt  = sm;                   // [128][GWS]  (k-major, local gate cols)
    float* xst = sm + 128 * GWS;       // [128][GXS]  (d-major, tt cols)
    __shared__ float bsm[128];

    const int b = blockIdx.x, dir = blockIdx.y;
    const int gh = blockIdx.z & 1;
    const int tch = blockIdx.z >> 1;   // 0..3
    const int tid = threadIdx.x;
    const int gq = tid & 31;           // gate quad within half
    const int tq = tid >> 5;           // 0..7 (8 t per thread)
    const int gl0 = 4 * gq;            // local gate base
    const int g0 = gh * 128 + gl0;     // global gate base

    // Stage W transposed (one-time): Wt[k][gl] = W[gh*128+gl][k]
    const float* wp = w + ((size_t)((layer - 1) * 2 + dir)) * GG * DH
                        + (size_t)gh * 128 * DH;
    for (int e = tid; e < 128 * DH; e += 256) {
        int g = e >> 7, k = e & 127;
        Wt[k * GWS + g] = wp[e];
    }
    if (tid < 128)
        bsm[tid] = bih[(layer * 2 + dir) * GG + gh * 128 + tid]
                 + bhh[(layer * 2 + dir) * GG + gh * 128 + tid];

    const float* inT = g_hT[insel] + (size_t)b * DH * TT;  // [d][t]
    float* outp = g_xw + ((size_t)(dir * BB + b)) * TT * GG;

    const int tbase = tch * 256;                   // multiple of 64 (aligned)
    const int tend  = (tbase + 256 < TT) ? (tbase + 256) : TT;

    // staging-load indices for this thread (8 float4 per tile)
    const int sd0 = tid >> 4;          // d base (stride 16 over f-index)
    const int st4 = tid & 15;          // t4 slot

    // Prologue: load tile 0 into regs, store, barrier.
    float4 nx[8];
#pragma unroll
    for (int i = 0; i < 8; i++) {
        int d = sd0 + i * 16;
        int tg = tbase + 4 * st4;
        nx[i] = (tg + 3 < TT)
            ? *(const float4*)(inT + (size_t)d * TT + tg)
            : make_float4(0.f, 0.f, 0.f, 0.f);
    }
    __syncthreads();   // also covers Wt/bsm staging
#pragma unroll
    for (int i = 0; i < 8; i++)
        *(float4*)(xst + (sd0 + i * 16) * GXS + 4 * st4) = nx[i];
    __syncthreads();

    for (int tc = tbase; tc < tend; tc += 64) {
        const bool have_next = (tc + 64 < tend);
        // Issue next tile's loads early (latency overlapped with compute)
        if (have_next) {
#pragma unroll
            for (int i = 0; i < 8; i++) {
                int d = sd0 + i * 16;
                int tg = tc + 64 + 4 * st4;
                nx[i] = (tg + 3 < TT)
                    ? *(const float4*)(inT + (size_t)d * TT + tg)
                    : make_float4(0.f, 0.f, 0.f, 0.f);
            }
        }

        u64 acc[4][4];
#pragma unroll
        for (int g = 0; g < 4; g++) {
            u64 bsp = splat2(bsm[gl0 + g]);
#pragma unroll
            for (int tp = 0; tp < 4; tp++) acc[g][tp] = bsp;
        }

#pragma unroll 8
        for (int k = 0; k < 128; k++) {
            float4 w4 = *(const float4*)(Wt + k * GWS + gl0);
            const ulonglong2* xp = (const ulonglong2*)(xst + k * GXS + tq * 8);
            ulonglong2 xA = xp[0], xB = xp[1];
            u64 x2[4] = {xA.x, xA.y, xB.x, xB.y};
            u64 ws[4] = {splat2(w4.x), splat2(w4.y), splat2(w4.z), splat2(w4.w)};
#pragma unroll
            for (int g = 0; g < 4; g++)
#pragma unroll
                for (int tp = 0; tp < 4; tp++)
                    acc[g][tp] = fma2(x2[tp], ws[g], acc[g][tp]);
        }

#pragma unroll
        for (int tp = 0; tp < 4; tp++) {
            float lo[4], hi[4];
#pragma unroll
            for (int g = 0; g < 4; g++) unpack2(acc[g][tp], lo[g], hi[g]);
            int t0 = tc + tq * 8 + 2 * tp;
            if (t0 < tend)
                *(float4*)(outp + (size_t)t0 * GG + g0) =
                    make_float4(lo[0], lo[1], lo[2], lo[3]);
            if (t0 + 1 < tend)
                *(float4*)(outp + (size_t)(t0 + 1) * GG + g0) =
                    make_float4(hi[0], hi[1], hi[2], hi[3]);
        }
        __syncthreads();   // everyone done reading xst
        if (have_next) {
#pragma unroll
            for (int i = 0; i < 8; i++)
                *(float4*)(xst + (sd0 + i * 16) * GXS + 4 * st4) = nx[i];
        }
        __syncthreads();   // xst ready for next tile
    }
}

// ---------------------------------------------------------------------------
// Recurrent scan v7 (FROZEN from R8): v6 reduction/tail + k-pair-packed h
// loads. grid (B/2, 2), 256 threads, 2 blocks/SM, one barrier per step.
// ---------------------------------------------------------------------------
#define HROW 80
#define HBUF (2 * HROW)

__global__ __launch_bounds__(256, 2) void lstm_recur_kernel(
    const float* __restrict__ whh,     // (4, 2, 256, 64)
    int layer, int outsel)
{
    __shared__ __align__(16) float hs2[2 * HBUF];    // double buffer

    const int dir = blockIdx.y;
    const int b0 = blockIdx.x * 2;
    const int tid = threadIdx.x;
    const int lane = tid & 31;
    const int j_lo = lane & 7;
    const int ks   = lane >> 3;          // k-slice 0..3
    const int j_hi = tid >> 5;           // warp 0..7
    const int j    = j_hi * 8 + j_lo;    // hidden unit 0..63

    // W rows for 4 gates, k-pair packed, this k-slice: 32 u64 regs
    u64 wg[4][8];
    {
        const float* wb = whh + (size_t)(layer * 2 + dir) * GG * HH;
#pragma unroll
        for (int g = 0; g < 4; g++) {
            const float2* wr = (const float2*)(wb + ((size_t)(g * 64 + j)) * HH + ks * 16);
#pragma unroll
            for (int p = 0; p < 8; p++) {
                float2 v = wr[p];
                wg[g][p] = pack2(v.x, v.y);
            }
        }
    }

    for (int e = tid; e < 2 * HBUF; e += 256) hs2[e] = 0.0f;

    const bool act = (ks < 2);
    const int bl = ks & 1;               // owned local batch (if act)
    const float* xwp = g_xw + ((size_t)(dir * BB + b0 + bl)) * TT * GG + j;
    float* houtTp = g_hT[outsel] + ((size_t)(b0 + bl) * DH + dir * HH + j) * TT;
    float c = 0.0f;

    __syncthreads();

    // prefetch xw for step 0
    float nx_i = 0.f, nx_f = 0.f, nx_g = 0.f, nx_o = 0.f;
    if (act) {
        int t0 = dir ? (TT - 1) : 0;
        const float* xp = xwp + (size_t)t0 * GG;
        nx_i = xp[0]; nx_f = xp[64]; nx_g = xp[128]; nx_o = xp[192];
    }

    const int rdoff = ks * 20;                       // k-slice offset in row
    const int wroff = bl * HROW + (j >> 4) * 20 + (j & 15);

    for (int s = 0; s < TT; s++) {
        const int t = dir ? (TT - 1 - s) : s;
        float cx_i = nx_i, cx_f = nx_f, cx_g = nx_g, cx_o = nx_o;
        if (act && s + 1 < TT) {
            int tn = dir ? (t - 1) : (t + 1);
            const float* xp = xwp + (size_t)tn * GG;
            nx_i = xp[0]; nx_f = xp[64]; nx_g = xp[128]; nx_o = xp[192];
        }

        const float* hb = hs2 + ((s + 1) & 1) * HBUF + rdoff;
        const ulonglong2* h0p = (const ulonglong2*)hb;          // batch 0
        const ulonglong2* h1p = (const ulonglong2*)(hb + HROW); // batch 1

        u64 z = pack2(0.f, 0.f);
        u64 acc[4][2];
#pragma unroll
        for (int g = 0; g < 4; g++) { acc[g][0] = z; acc[g][1] = z; }

#pragma unroll
        for (int q = 0; q < 4; q++) {
            ulonglong2 h0 = h0p[q];   // k-pairs 2q, 2q+1 of batch 0
            ulonglong2 h1 = h1p[q];
#pragma unroll
            for (int g = 0; g < 4; g++) {
                acc[g][0] = fma2(h0.x, wg[g][2 * q],     acc[g][0]);
                acc[g][0] = fma2(h0.y, wg[g][2 * q + 1], acc[g][0]);
                acc[g][1] = fma2(h1.x, wg[g][2 * q],     acc[g][1]);
                acc[g][1] = fma2(h1.y, wg[g][2 * q + 1], acc[g][1]);
            }
        }

        // horizontal k-pair add -> 8 scalars, then pack by (gate-pair, batch)
        float sv[4][2];
#pragma unroll
        for (int g = 0; g < 4; g++)
#pragma unroll
            for (int bb = 0; bb < 2; bb++) {
                float lo, hi; unpack2(acc[g][bb], lo, hi);
                sv[g][bb] = lo + hi;
            }
        u64 P0 = pack2(sv[0][0], sv[1][0]);  // (i,f) batch0
        u64 Q0 = pack2(sv[2][0], sv[3][0]);  // (g,o) batch0
        u64 P1 = pack2(sv[0][1], sv[1][1]);
        u64 Q1 = pack2(sv[2][1], sv[3][1]);

        // full butterfly over the 4 k-slices (independent chains)
        P0 = shfl_add2(P0, 8); P0 = shfl_add2(P0, 16);
        Q0 = shfl_add2(Q0, 8); Q0 = shfl_add2(Q0, 16);
        P1 = shfl_add2(P1, 8); P1 = shfl_add2(P1, 16);
        Q1 = shfl_add2(Q1, 8); Q1 = shfl_add2(Q1, 16);

        if (act) {
            u64 a01 = bl ? P1 : P0;
            u64 a23 = bl ? Q1 : Q0;
            float ai, af, ag, ao;
            unpack2(a01, ai, af);
            unpack2(a23, ag, ao);
            ai += cx_i; af += cx_f; ag += cx_g; ao += cx_o;
            float gi = fast_sig(ai);
            float gf = fast_sig(af);
            float gv = fast_tanh(ag);
            float go = fast_sig(ao);
            c = fmaf(gf, c, gi * gv);
            float h = go * fast_tanh(c);
            hs2[(s & 1) * HBUF + wroff] = h;
            houtTp[t] = h;
        }
        __syncthreads();
    }
}

// ---------------------------------------------------------------------------
// Final linear head on last timestep of layer-3 output (g_hT[1]).
// ---------------------------------------------------------------------------
__global__ __launch_bounds__(64) void head_kernel(
    const float* __restrict__ wl,      // (54, 128)
    const float* __restrict__ bl,      // (54,)
    float* __restrict__ out)           // (B, 54)
{
    const int b = blockIdx.x;
    __shared__ float hsm[DH];
    const int tid = threadIdx.x;
    const float* hin = g_hT[1];
    for (int e = tid; e < DH; e += 64)
        hsm[e] = hin[((size_t)b * DH + e) * TT + (TT - 1)];
    __syncthreads();
    if (tid < 54) {
        float acc = bl[tid];
#pragma unroll
        for (int k = 0; k < DH; k++) acc = fmaf(hsm[k], wl[tid * DH + k], acc);
        out[b * 54 + tid] = acc;
    }
}

// ---------------------------------------------------------------------------
extern "C" void kernel_launch(void* const* d_in, const int* in_sizes, int n_in,
                              void* d_out, int out_size)
{
    (void)in_sizes; (void)n_in; (void)out_size;
    const float* x      = (const float*)d_in[0];
    const float* w_ih_f = (const float*)d_in[1];
    const float* w_ih_r = (const float*)d_in[2];
    const float* w_hh   = (const float*)d_in[3];
    const float* b_ih   = (const float*)d_in[4];
    const float* b_hh   = (const float*)d_in[5];
    const float* w_lin  = (const float*)d_in[6];
    const float* b_lin  = (const float*)d_in[7];
    float* out = (float*)d_out;

    cudaFuncSetAttribute(gemm_rest_kernel,
                         cudaFuncAttributeMaxDynamicSharedMemorySize, GEMM_SMEM);

    dim3 grid0(BB, 2, 4);     // (batch, dir, tchunk)
    dim3 gridG(BB, 2, 8);     // (batch, dir, gh + 2*tchunk)
    dim3 gridR(BB / 2, 2);    // 256 blocks, 2 batches each

    // Layer 0
    gemm0_kernel<<<grid0, 256>>>(x, w_ih_f, b_ih, b_hh);
    lstm_recur_kernel<<<gridR, 256>>>(w_hh, 0, 0);

    // Layers 1..3
    for (int l = 1; l < 4; l++) {
        gemm_rest_kernel<<<gridG, 256, GEMM_SMEM>>>(w_ih_r, b_ih, b_hh, l, (l - 1) & 1);
        lstm_recur_kernel<<<gridR, 256>>>(w_hh, l, l & 1);
    }

    // Head
    head_kernel<<<BB, 64>>>(w_lin, b_lin, out);
}